// round 7
// baseline (speedup 1.0000x reference)
#include <cuda_runtime.h>
#include <math.h>
#include <stdint.h>

// Problem constants
#define Bq   2
#define Pq   4000
#define NPq  4096
#define Mq   512
#define HWq  214272            // 496 * 432

// Output section offsets (in floats)
static constexpr long O1 = (long)Bq * 128 * HWq;          // spatial_features_point
static constexpr long O2 = 2 * O1;                        // spatial_scale_features
static constexpr long O3 = O2 + (long)Bq * 64 * HWq;      // point_positive_features
static constexpr long O4 = O3 + (long)Bq * Pq * 64;       // memory_positive_features

// Zero-fill split between the two fused kernels (in float4 units)
static constexpr long N4ALL = O3 / 4;
static constexpr long N4P   = (N4ALL / 16) * 13;          // points kernel share
static constexpr long N4M   = N4ALL - N4P;                // memory kernel share

// Winner map for duplicate-index resolution (last-write-wins => max pillar idx)
__device__ int g_winner[Bq * HWq];

__global__ void winner_reset_kernel() {
    int i = blockIdx.x * blockDim.x + threadIdx.x;
    if (i < Bq * HWq) g_winner[i] = -1;
}

__global__ void winner_mark_kernel(const int* __restrict__ idxs) {
    int i = blockIdx.x * blockDim.x + threadIdx.x;
    if (i < Bq * Pq) {
        int b = i / Pq;
        int p = i - b * Pq;
        atomicMax(&g_winner[b * HWq + idxs[i]], p);
    }
}

// ---------------------------------------------------------------------------
// Packed f32x2 FMA (Blackwell): d = a * b + d, elementwise on two fp32 lanes.
// ---------------------------------------------------------------------------
__device__ __forceinline__ void ffma2(unsigned long long& d,
                                      unsigned long long a,
                                      unsigned long long b) {
    asm("fma.rn.f32x2 %0, %1, %2, %0;" : "+l"(d) : "l"(a), "l"(b));
}

__device__ __forceinline__ float lo_f(unsigned long long u) {
    return __uint_as_float((unsigned)(u & 0xffffffffu));
}
__device__ __forceinline__ float hi_f(unsigned long long u) {
    return __uint_as_float((unsigned)(u >> 32));
}

// Fully-unrolled top-8 insertion (registers only; sorted descending)
__device__ __forceinline__ void top8_insert(float (&tv)[8], int (&ti)[8], float v, int n) {
    if (v > tv[7]) {
#pragma unroll
        for (int s = 0; s < 8; ++s) {
            if (v > tv[s]) {
                float a = tv[s]; int b = ti[s];
                tv[s] = v; ti[s] = n;
                v = a; n = b;
            }
        }
    }
}

// ---------------------------------------------------------------------------
// Fused GEMM + top-8 + softmax + weighted gather (+ paced zero-fill of the
// dense spatial output region, which is otherwise a dedicated DRAM-bound pass).
//
// Block: 128 threads (4 warps). Tile: 16 pillars x 256 points.
// Warp w owns pillars 4w..4w+3 (broadcast reads); lane l owns points
// {l + 32j, j=0..7} of each tile. Dot products run along k in f32x2 pairs.
// smem: sX [256][68] n-major (natural layout, conflict-free), sP [16][68].
// ---------------------------------------------------------------------------
#define XSTRIDE 68
#define SMEM_FLOATS (256 * XSTRIDE + 16 * XSTRIDE)   // 18496 floats = 73984 B

template<int NTILES>
__global__ __launch_bounds__(128, 3) void topk_agg_kernel(
    const float* __restrict__ pillars,  // [B, P, 64]
    const float* __restrict__ X,        // [B, N, 64] or [N, 64] (xStride = 0)
    float* __restrict__ outp,           // [B, P, 64]
    int xStride,
    float4* __restrict__ zbase, long zcount)
{
    extern __shared__ float smem[];
    float* sX = smem;                        // [256][68]
    float* sP = smem + 256 * XSTRIDE;        // [16][68]

    const int b = blockIdx.y;
    const int pBase = blockIdx.x * 16;
    const float* pil = pillars + (size_t)b * Pq * 64;
    const float* Xb  = X + (size_t)b * xStride;
    float* outb = outp + (size_t)b * Pq * 64;

    const int tid  = threadIdx.x;
    const int lane = tid & 31;
    const int warp = tid >> 5;

    // Zero-fill slice bookkeeping (paced per tile)
    const long nBlocks = (long)gridDim.x * gridDim.y;
    const long blin = (long)blockIdx.y * gridDim.x + blockIdx.x;
    const long zpb = (zcount + nBlocks - 1) / nBlocks;        // per block
    const long zbeg = blin * zpb;
    const long zend = (zbeg + zpb < zcount) ? (zbeg + zpb) : zcount;
    const long zpt = (zpb + NTILES - 1) / NTILES;             // per tile
    const float4 z4 = make_float4(0.f, 0.f, 0.f, 0.f);

    // Load pillar tile [16][64] (m-major, natural float4s)
#pragma unroll
    for (int i = 0; i < 2; i++) {
        int lin = tid + 128 * i;
        int m = lin >> 4, k4 = lin & 15;
        float4 f = ((const float4*)pil)[(size_t)(pBase + m) * 16 + k4];
        *(float4*)&sP[m * XSTRIDE + 4 * k4] = f;
    }

    // Per-lane top-8 lists for the 4 pillars this warp owns
    float topv[4][8]; int topi[4][8];
#pragma unroll
    for (int a = 0; a < 4; a++)
#pragma unroll
        for (int s = 0; s < 8; s++) { topv[a][s] = -INFINITY; topi[a][s] = 0; }

    const float* sPw = sP + warp * (4 * XSTRIDE);
    const float* sXl = sX + lane * XSTRIDE;

    for (int tile = 0; tile < NTILES; tile++) {
        const int nB = tile * 256;
        __syncthreads();
        // Load X tile [256][64] into n-major smem (coalesced, conflict-free)
#pragma unroll
        for (int i = 0; i < 32; i++) {
            int lin = tid + 128 * i;
            int n = lin >> 4, k4 = lin & 15;
            float4 f = ((const float4*)Xb)[(size_t)(nB + n) * 16 + k4];
            *(float4*)&sX[n * XSTRIDE + 4 * k4] = f;
        }
        __syncthreads();

        // Paced zero-fill chunk (fire-and-forget DRAM writes under compute)
        {
            long tb = zbeg + (long)tile * zpt;
            long te = tb + zpt; if (te > zend) te = zend;
            for (long i = tb + tid; i < te; i += 128) zbase[i] = z4;
        }

        // acc[a][j]: f32x2 pair over (even k, odd k) for pillar a, point j
        unsigned long long acc[4][8];
#pragma unroll
        for (int a = 0; a < 4; a++)
#pragma unroll
            for (int j = 0; j < 8; j++) acc[a][j] = 0ull;

#pragma unroll 4
        for (int k4 = 0; k4 < 16; k4++) {
            ulonglong2 p0 = *(const ulonglong2*)&sPw[              4 * k4];
            ulonglong2 p1 = *(const ulonglong2*)&sPw[    XSTRIDE + 4 * k4];
            ulonglong2 p2 = *(const ulonglong2*)&sPw[2 * XSTRIDE + 4 * k4];
            ulonglong2 p3 = *(const ulonglong2*)&sPw[3 * XSTRIDE + 4 * k4];
#pragma unroll
            for (int j = 0; j < 8; j++) {
                ulonglong2 x = *(const ulonglong2*)&sXl[j * (32 * XSTRIDE) + 4 * k4];
                ffma2(acc[0][j], p0.x, x.x); ffma2(acc[0][j], p0.y, x.y);
                ffma2(acc[1][j], p1.x, x.x); ffma2(acc[1][j], p1.y, x.y);
                ffma2(acc[2][j], p2.x, x.x); ffma2(acc[2][j], p2.y, x.y);
                ffma2(acc[3][j], p3.x, x.x); ffma2(acc[3][j], p3.y, x.y);
            }
        }

        // Fold pairs -> logits, stream into top-8 lists
#pragma unroll
        for (int j = 0; j < 8; j++) {
            int n = nB + lane + 32 * j;
#pragma unroll
            for (int a = 0; a < 4; a++) {
                float v = lo_f(acc[a][j]) + hi_f(acc[a][j]);
                top8_insert(topv[a], topi[a], v, n);
            }
        }
    }

    // ---- merge phase (reuse sX region) ----
    __syncthreads();
    float* candV = smem;                       // [16][264]
    int*   candI = (int*)(smem + 16 * 264);    // [16][264]
    float* s1V   = smem + 2 * 16 * 264;        // [16][8][8]
    int*   s1I   = (int*)(smem + 2 * 16 * 264 + 16 * 64);
    float* wV    = smem + 2 * 16 * 264 + 2 * 16 * 64;   // [16][8]
    int*   wI    = (int*)(smem + 2 * 16 * 264 + 2 * 16 * 64 + 16 * 8);

#pragma unroll
    for (int a = 0; a < 4; a++) {
        int m = 4 * warp + a;
#pragma unroll
        for (int s = 0; s < 8; s++) {
            candV[m * 264 + lane * 8 + s] = topv[a][s];
            candI[m * 264 + lane * 8 + s] = topi[a][s];
        }
    }
    __syncthreads();

    // Stage 1: 8 threads per pillar, each merges 32 candidates -> top-8
    {
        int m = tid >> 3, part = tid & 7;
        float fv[8]; int fi[8];
#pragma unroll
        for (int s = 0; s < 8; s++) { fv[s] = -INFINITY; fi[s] = 0; }
        for (int t = 0; t < 32; t++) {
            int c = part + 8 * t;
            top8_insert(fv, fi, candV[m * 264 + c], candI[m * 264 + c]);
        }
#pragma unroll
        for (int s = 0; s < 8; s++) {
            s1V[m * 64 + part * 8 + s] = fv[s];
            s1I[m * 64 + part * 8 + s] = fi[s];
        }
    }
    __syncthreads();

    // Stage 2: one thread per pillar merges 64 -> final top-8 -> softmax
    if (tid < 16) {
        int m = tid;
        float fv[8]; int fi[8];
#pragma unroll
        for (int s = 0; s < 8; s++) { fv[s] = -INFINITY; fi[s] = 0; }
        for (int c = 0; c < 64; c++)
            top8_insert(fv, fi, s1V[m * 64 + c], s1I[m * 64 + c]);
        float w[8]; float sum = 0.f;
#pragma unroll
        for (int s = 0; s < 8; s++) { w[s] = expf(fv[s] - fv[0]); sum += w[s]; }
        float inv = 1.f / sum;
#pragma unroll
        for (int s = 0; s < 8; s++) { wV[m * 8 + s] = w[s] * inv; wI[m * 8 + s] = fi[s]; }
    }
    __syncthreads();

    // Weighted gather: out[p][d] = sum_k w_k * X[idx_k][d]  (X rows are L2-hot)
#pragma unroll
    for (int i = 0; i < 8; i++) {
        int lin = tid + 128 * i;
        int m = lin >> 6, d = lin & 63;
        float s = 0.f;
#pragma unroll
        for (int kk = 0; kk < 8; kk++)
            s += wV[m * 8 + kk] * Xb[(size_t)wI[m * 8 + kk] * 64 + d];
        outb[(size_t)(pBase + m) * 64 + d] = s;
    }
}

// ---------------------------------------------------------------------------
// Scatter: winner pillar per BEV column writes the three dense grids.
// ---------------------------------------------------------------------------
__global__ __launch_bounds__(64) void scatter_kernel(
    const float* __restrict__ pillars, const float* __restrict__ scales,
    const float* __restrict__ posP,    const float* __restrict__ posM,
    const int* __restrict__ idxs,      float* __restrict__ out)
{
    int bp = blockIdx.x;
    int b = bp / Pq, p = bp - b * Pq;
    int col = idxs[bp];
    if (g_winner[b * HWq + col] != p) return;
    int d = threadIdx.x;

    size_t o = (size_t)bp * 64 + d;
    float pilv = pillars[o];
    float scv  = scales[o];
    float ppv  = posP[o];
    float pmv  = posM[o];

    float* sp  = out;               // spatial_features       [B,128,HW]: [pillars ; pos_mem]
    float* spp = out + (size_t)O1;  // spatial_features_point [B,128,HW]: [pillars ; pos_point]
    float* sps = out + (size_t)O2;  // spatial_scale_features [B, 64,HW]

    size_t base = (size_t)b * 128 * HWq + (size_t)d * HWq + col;
    sp [base] = pilv;
    sp [base + (size_t)64 * HWq] = pmv;
    spp[base] = pilv;
    spp[base + (size_t)64 * HWq] = ppv;
    sps[(size_t)b * 64 * HWq + (size_t)d * HWq + col] = scv;
}

// ---------------------------------------------------------------------------
extern "C" void kernel_launch(void* const* d_in, const int* in_sizes, int n_in,
                              void* d_out, int out_size) {
    (void)in_sizes; (void)n_in; (void)out_size;
    const float* pillars = (const float*)d_in[0];   // [B,P,64]
    const float* scales  = (const float*)d_in[1];   // [B,P,64]
    const float* points  = (const float*)d_in[2];   // [B,NP,64]
    const float* W       = (const float*)d_in[3];   // [M,64]
    const int*   idxs    = (const int*)d_in[4];     // [B,P]
    float* out = (float*)d_out;

    const int smemBytes = SMEM_FLOATS * 4;          // 73984 B
    cudaFuncSetAttribute(topk_agg_kernel<16>,
                         cudaFuncAttributeMaxDynamicSharedMemorySize, smemBytes);
    cudaFuncSetAttribute(topk_agg_kernel<2>,
                         cudaFuncAttributeMaxDynamicSharedMemorySize, smemBytes);

    // 1) duplicate-index winner resolution (last-write-wins => max p)
    winner_reset_kernel<<<(Bq * HWq + 255) / 256, 256>>>();
    winner_mark_kernel<<<(Bq * Pq + 255) / 256, 256>>>(idxs);

    // 2) fused attention stages; each also zero-fills its share of the
    //    dense spatial region under its compute (DRAM was idle there).
    dim3 grid(Pq / 16, Bq);   // 250 x 2 = 500 blocks
    topk_agg_kernel<16><<<grid, 128, smemBytes>>>(
        pillars, points, out + O3, NPq * 64, (float4*)out, N4P);
    topk_agg_kernel<2><<<grid, 128, smemBytes>>>(
        pillars, W,      out + O4, 0,        (float4*)out + N4P, N4M);

    // 3) scatter winners into the dense BEV grids
    scatter_kernel<<<Bq * Pq, 64>>>(pillars, scales, out + O3, out + O4, idxs, out);
}

// round 9
// speedup vs baseline: 1.3167x; 1.3167x over previous
#include <cuda_runtime.h>
#include <math.h>
#include <stdint.h>

// Problem constants
#define Bq   2
#define Pq   4000
#define NPq  4096
#define Mq   512
#define HWq  214272            // 496 * 432

// Output section offsets (in floats)
static constexpr long O1 = (long)Bq * 128 * HWq;          // spatial_features_point
static constexpr long O2 = 2 * O1;                        // spatial_scale_features
static constexpr long O3 = O2 + (long)Bq * 64 * HWq;      // point_positive_features
static constexpr long O4 = O3 + (long)Bq * Pq * 64;       // memory_positive_features

// Zero-fill split between the two fused kernels (in float4 units)
static constexpr long N4ALL = O3 / 4;
static constexpr long N4P   = (N4ALL / 8) * 7;            // points kernel share
static constexpr long N4M   = N4ALL - N4P;                // memory kernel share

// Winner map for duplicate-index resolution (last-write-wins => max pillar idx)
__device__ int g_winner[Bq * HWq];

__global__ void winner_reset_kernel() {
    int i = blockIdx.x * blockDim.x + threadIdx.x;
    if (i < Bq * HWq) g_winner[i] = -1;
}

__global__ void winner_mark_kernel(const int* __restrict__ idxs) {
    int i = blockIdx.x * blockDim.x + threadIdx.x;
    if (i < Bq * Pq) {
        int b = i / Pq;
        int p = i - b * Pq;
        atomicMax(&g_winner[b * HWq + idxs[i]], p);
    }
}

// ---------------------------------------------------------------------------
// Packed f32x2 helpers (Blackwell)
// ---------------------------------------------------------------------------
__device__ __forceinline__ void ffma2(unsigned long long& d,
                                      unsigned long long a,
                                      unsigned long long b) {
    asm("fma.rn.f32x2 %0, %1, %2, %0;" : "+l"(d) : "l"(a), "l"(b));
}
__device__ __forceinline__ unsigned long long pack2(float a, float b) {
    unsigned long long r;
    asm("mov.b64 %0, {%1, %2};" : "=l"(r) : "f"(a), "f"(b));
    return r;
}
__device__ __forceinline__ float pairsum(unsigned long long u) {
    float lo, hi;
    asm("mov.b64 {%0, %1}, %2;" : "=f"(lo), "=f"(hi) : "l"(u));
    return lo + hi;
}

// Fully-unrolled top-8 insertion (registers only; sorted descending)
__device__ __forceinline__ void top8_insert(float (&tv)[8], int (&ti)[8], float v, int n) {
    if (v > tv[7]) {
#pragma unroll
        for (int s = 0; s < 8; ++s) {
            if (v > tv[s]) {
                float a = tv[s]; int b = ti[s];
                tv[s] = v; ti[s] = n;
                v = a; n = b;
            }
        }
    }
}

// ---------------------------------------------------------------------------
// Register-stationary fused GEMM + top-8 + softmax + gather (+ paced zero-fill).
//
// Block: 256 threads (8 warps), 32 pillars. Lane l of every warp owns pillar
// pBase+l fully in registers (32 f32x2 pairs). Each tile stages 128 X rows in
// smem; warp w processes rows [16w, 16w+16) of the tile via BROADCAST reads
// (whole warp same address -> conflict-free). One logit per (lane, row),
// streamed into a per-lane top-8. Block-end: 8 warp-lists per pillar merged,
// softmax over final top-8, weighted gather of X rows from global (L2-hot).
// ---------------------------------------------------------------------------
#define SMEM_BYTES 33024   // 128*64 floats X tile; merge phase reuses it

template<int NROWTILES>   // N / 128
__global__ __launch_bounds__(256, 2) void topk_warp_kernel(
    const float* __restrict__ pillars,  // [B, P, 64]
    const float* __restrict__ X,        // [B, N, 64] or [N, 64] (xStride = 0)
    float* __restrict__ outp,           // [B, P, 64]
    int xStride,
    float4* __restrict__ zbase, long zcount)
{
    extern __shared__ float smem[];
    float* sX = smem;                               // [128][64]

    const int b = blockIdx.y;
    const int pBase = blockIdx.x * 32;
    const float* pil = pillars + (size_t)b * Pq * 64;
    const float* Xb  = X + (size_t)b * xStride;
    float* outb = outp + (size_t)b * Pq * 64;

    const int tid  = threadIdx.x;
    const int lane = tid & 31;
    const int warp = tid >> 5;

    // Lane-private pillar row in registers as 32 f32x2 pairs
    unsigned long long pk[32];
    {
        const float4* prow = (const float4*)(pil + (size_t)(pBase + lane) * 64);
#pragma unroll
        for (int i = 0; i < 16; i++) {
            float4 f = prow[i];
            pk[2 * i]     = pack2(f.x, f.y);
            pk[2 * i + 1] = pack2(f.z, f.w);
        }
    }

    float topv[8]; int topi[8];
#pragma unroll
    for (int s = 0; s < 8; s++) { topv[s] = -INFINITY; topi[s] = 0; }

    // Zero-fill slice bookkeeping (paced per tile)
    const long nBlocks = (long)gridDim.x * gridDim.y;
    const long blin = (long)blockIdx.y * gridDim.x + blockIdx.x;
    const long zpb = (zcount + nBlocks - 1) / nBlocks;
    const long zbeg = blin * zpb;
    const long zend = (zbeg + zpb < zcount) ? (zbeg + zpb) : zcount;
    const long zpt = (zpb + NROWTILES - 1) / NROWTILES;
    const float4 z4 = make_float4(0.f, 0.f, 0.f, 0.f);

    for (int tile = 0; tile < NROWTILES; tile++) {
        __syncthreads();
        // Cooperative coalesced load of 128 X rows (32 KB)
        {
            const float4* xsrc = (const float4*)Xb + (size_t)tile * (128 * 16);
            float4* xdst = (float4*)sX;
#pragma unroll
            for (int i = 0; i < 8; i++) xdst[tid + 256 * i] = xsrc[tid + 256 * i];
        }
        __syncthreads();

        // Paced zero-fill chunk (fire-and-forget stores drain under compute)
        {
            long tb = zbeg + (long)tile * zpt;
            long te = tb + zpt; if (te > zend) te = zend;
            for (long i = tb + tid; i < te; i += 256) zbase[i] = z4;
        }

        // Warp w processes rows [16w, 16w+16) of this tile; broadcast reads.
        const ulonglong2* xrow = (const ulonglong2*)(sX + warp * (16 * 64));
        const int nbase = tile * 128 + warp * 16;
#pragma unroll 2
        for (int r = 0; r < 16; r++) {
            unsigned long long acc0 = 0ull, acc1 = 0ull;
            const ulonglong2* xr = xrow + r * 16;   // 16 ulonglong2 per 64-float row
#pragma unroll
            for (int k8 = 0; k8 < 16; k8++) {
                ulonglong2 x = xr[k8];              // floats k = 4*k8 .. 4*k8+3
                ffma2(acc0, pk[2 * k8],     x.x);   // pairs (4k8, 4k8+1)
                ffma2(acc1, pk[2 * k8 + 1], x.y);   // pairs (4k8+2, 4k8+3)
            }
            float v = pairsum(acc0) + pairsum(acc1);
            top8_insert(topv, topi, v, nbase + r);
        }
    }

    // ---- merge phase (reuse sX region) ----
    __syncthreads();
    float* candV = smem;                         // [32][65] padded
    int*   candI = (int*)(smem + 32 * 65);       // [32][65]
    float* wV    = smem + 2 * 32 * 65;           // [32][8]
    int*   wI    = (int*)(smem + 2 * 32 * 65 + 32 * 8);

#pragma unroll
    for (int s = 0; s < 8; s++) {
        candV[lane * 65 + warp * 8 + s] = topv[s];
        candI[lane * 65 + warp * 8 + s] = topi[s];
    }
    __syncthreads();

    // One thread per pillar merges 64 candidates -> final top-8 -> softmax
    if (tid < 32) {
        int m = tid;
        float fv[8]; int fi[8];
#pragma unroll
        for (int s = 0; s < 8; s++) { fv[s] = -INFINITY; fi[s] = 0; }
        for (int c = 0; c < 64; c++)
            top8_insert(fv, fi, candV[m * 65 + c], candI[m * 65 + c]);
        float w[8]; float sum = 0.f;
#pragma unroll
        for (int s = 0; s < 8; s++) { w[s] = expf(fv[s] - fv[0]); sum += w[s]; }
        float inv = 1.f / sum;
#pragma unroll
        for (int s = 0; s < 8; s++) { wV[m * 8 + s] = w[s] * inv; wI[m * 8 + s] = fi[s]; }
    }
    __syncthreads();

    // Weighted gather: out[p][d] = sum_k w_k * X[idx_k][d]  (rows are L2-hot)
#pragma unroll
    for (int i = 0; i < 8; i++) {
        int lin = tid + 256 * i;
        int m = lin >> 6, d = lin & 63;
        float s = 0.f;
#pragma unroll
        for (int kk = 0; kk < 8; kk++)
            s += wV[m * 8 + kk] * Xb[(size_t)wI[m * 8 + kk] * 64 + d];
        outb[(size_t)(pBase + m) * 64 + d] = s;
    }
}

// ---------------------------------------------------------------------------
// Scatter: winner pillar per BEV column writes the three dense grids.
// ---------------------------------------------------------------------------
__global__ __launch_bounds__(64) void scatter_kernel(
    const float* __restrict__ pillars, const float* __restrict__ scales,
    const float* __restrict__ posP,    const float* __restrict__ posM,
    const int* __restrict__ idxs,      float* __restrict__ out)
{
    int bp = blockIdx.x;
    int b = bp / Pq, p = bp - b * Pq;
    int col = idxs[bp];
    if (g_winner[b * HWq + col] != p) return;
    int d = threadIdx.x;

    size_t o = (size_t)bp * 64 + d;
    float pilv = pillars[o];
    float scv  = scales[o];
    float ppv  = posP[o];
    float pmv  = posM[o];

    float* sp  = out;               // spatial_features       [B,128,HW]: [pillars ; pos_mem]
    float* spp = out + (size_t)O1;  // spatial_features_point [B,128,HW]: [pillars ; pos_point]
    float* sps = out + (size_t)O2;  // spatial_scale_features [B, 64,HW]

    size_t base = (size_t)b * 128 * HWq + (size_t)d * HWq + col;
    sp [base] = pilv;
    sp [base + (size_t)64 * HWq] = pmv;
    spp[base] = pilv;
    spp[base + (size_t)64 * HWq] = ppv;
    sps[(size_t)b * 64 * HWq + (size_t)d * HWq + col] = scv;
}

// ---------------------------------------------------------------------------
extern "C" void kernel_launch(void* const* d_in, const int* in_sizes, int n_in,
                              void* d_out, int out_size) {
    (void)in_sizes; (void)n_in; (void)out_size;
    const float* pillars = (const float*)d_in[0];   // [B,P,64]
    const float* scales  = (const float*)d_in[1];   // [B,P,64]
    const float* points  = (const float*)d_in[2];   // [B,NP,64]
    const float* W       = (const float*)d_in[3];   // [M,64]
    const int*   idxs    = (const int*)d_in[4];     // [B,P]
    float* out = (float*)d_out;

    // 1) duplicate-index winner resolution (last-write-wins => max p)
    winner_reset_kernel<<<(Bq * HWq + 255) / 256, 256>>>();
    winner_mark_kernel<<<(Bq * Pq + 255) / 256, 256>>>(idxs);

    // 2) fused attention stages; each also zero-fills its share of the
    //    dense spatial region under its compute.
    dim3 grid(Pq / 32, Bq);   // 125 x 2 = 250 blocks
    topk_warp_kernel<NPq / 128><<<grid, 256, SMEM_BYTES>>>(
        pillars, points, out + O3, NPq * 64, (float4*)out, N4P);
    topk_warp_kernel<Mq / 128><<<grid, 256, SMEM_BYTES>>>(
        pillars, W,      out + O4, 0,        (float4*)out + N4P, N4M);

    // 3) scatter winners into the dense BEV grids
    scatter_kernel<<<Bq * Pq, 64>>>(pillars, scales, out + O3, out + O4, idxs, out);
}

// round 12
// speedup vs baseline: 1.4535x; 1.1039x over previous
#include <cuda_runtime.h>
#include <math.h>
#include <stdint.h>

// Problem constants
#define Bq   2
#define Pq   4000
#define NPq  4096
#define Mq   512
#define HWq  214272            // 496 * 432

// Output section offsets (in floats)
static constexpr long O1 = (long)Bq * 128 * HWq;          // spatial_features_point
static constexpr long O2 = 2 * O1;                        // spatial_scale_features
static constexpr long O3 = O2 + (long)Bq * 64 * HWq;      // point_positive_features
static constexpr long O4 = O3 + (long)Bq * Pq * 64;       // memory_positive_features

// Zero-fill split between the two fused kernels (in float4 units)
static constexpr long N4ALL = O3 / 4;
static constexpr long N4P   = (N4ALL / 8) * 7;            // points kernel share
static constexpr long N4M   = N4ALL - N4P;                // memory kernel share

// Winner map for duplicate-index resolution (last-write-wins => max pillar idx)
__device__ int g_winner[Bq * HWq];

__global__ void winner_reset_kernel() {
    int i = blockIdx.x * blockDim.x + threadIdx.x;
    if (i < Bq * HWq) g_winner[i] = -1;
}

__global__ void winner_mark_kernel(const int* __restrict__ idxs) {
    int i = blockIdx.x * blockDim.x + threadIdx.x;
    if (i < Bq * Pq) {
        int b = i / Pq;
        int p = i - b * Pq;
        atomicMax(&g_winner[b * HWq + idxs[i]], p);
    }
}

// ---------------------------------------------------------------------------
// Packed f32x2 helpers (Blackwell) + cp.async
// ---------------------------------------------------------------------------
__device__ __forceinline__ void ffma2(unsigned long long& d,
                                      unsigned long long a,
                                      unsigned long long b) {
    asm("fma.rn.f32x2 %0, %1, %2, %0;" : "+l"(d) : "l"(a), "l"(b));
}
__device__ __forceinline__ unsigned long long pack2(float a, float b) {
    unsigned long long r;
    asm("mov.b64 %0, {%1, %2};" : "=l"(r) : "f"(a), "f"(b));
    return r;
}
__device__ __forceinline__ float pairsum(unsigned long long u) {
    float lo, hi;
    asm("mov.b64 {%0, %1}, %2;" : "=f"(lo), "=f"(hi) : "l"(u));
    return lo + hi;
}
__device__ __forceinline__ uint32_t smem_u32(const void* p) {
    uint32_t a;
    asm("{ .reg .u64 t; cvta.to.shared.u64 t, %1; cvt.u32.u64 %0, t; }" : "=r"(a) : "l"(p));
    return a;
}
__device__ __forceinline__ void cp_async16(uint32_t saddr, const void* gptr) {
    asm volatile("cp.async.cg.shared.global [%0], [%1], 16;" :: "r"(saddr), "l"(gptr));
}
__device__ __forceinline__ void cp_commit() {
    asm volatile("cp.async.commit_group;");
}
template<int N>
__device__ __forceinline__ void cp_wait() {
    asm volatile("cp.async.wait_group %0;" :: "n"(N));
}

// Fully-unrolled top-8 insertion (registers only; sorted descending)
__device__ __forceinline__ void top8_insert(float (&tv)[8], int (&ti)[8], float v, int n) {
    if (v > tv[7]) {
#pragma unroll
        for (int s = 0; s < 8; ++s) {
            if (v > tv[s]) {
                float a = tv[s]; int b = ti[s];
                tv[s] = v; ti[s] = n;
                v = a; n = b;
            }
        }
    }
}

// ---------------------------------------------------------------------------
// Register-stationary fused GEMM + top-8 + softmax + gather (+ paced zero-fill)
// with cp.async double-buffered X tiles and two-row-interleaved FFMA2 chains.
//
// Block: 256 threads (8 warps), 32 pillars. Lane l owns pillar pBase+l fully
// in registers (32 f32x2 pairs). Tile = 128 X rows staged via cp.async into
// one of two 32KB smem buffers; warp w computes rows [16w,16w+16) of the
// CURRENT buffer (broadcast smem reads) while the NEXT tile streams in.
// ---------------------------------------------------------------------------
#define SMEM_BYTES 65536   // 2 x (128*64 floats); merge phase reuses buffer 0

template<int NROWTILES>   // N / 128
__global__ __launch_bounds__(256, 2) void topk_warp_kernel(
    const float* __restrict__ pillars,  // [B, P, 64]
    const float* __restrict__ X,        // [B, N, 64] or [N, 64] (xStride = 0)
    float* __restrict__ outp,           // [B, P, 64]
    int xStride,
    float4* __restrict__ zbase, long zcount)
{
    extern __shared__ float smem[];

    const int b = blockIdx.y;
    const int pBase = blockIdx.x * 32;
    const float* pil = pillars + (size_t)b * Pq * 64;
    const float* Xb  = X + (size_t)b * xStride;
    float* outb = outp + (size_t)b * Pq * 64;

    const int tid  = threadIdx.x;
    const int lane = tid & 31;
    const int warp = tid >> 5;

    // Lane-private pillar row in registers as 32 f32x2 pairs
    unsigned long long pk[32];
    {
        const float4* prow = (const float4*)(pil + (size_t)(pBase + lane) * 64);
#pragma unroll
        for (int i = 0; i < 16; i++) {
            float4 f = prow[i];
            pk[2 * i]     = pack2(f.x, f.y);
            pk[2 * i + 1] = pack2(f.z, f.w);
        }
    }

    float topv[8]; int topi[8];
#pragma unroll
    for (int s = 0; s < 8; s++) { topv[s] = -INFINITY; topi[s] = 0; }

    // Zero-fill slice bookkeeping (paced per tile)
    const long nBlocks = (long)gridDim.x * gridDim.y;
    const long blin = (long)blockIdx.y * gridDim.x + blockIdx.x;
    const long zpb = (zcount + nBlocks - 1) / nBlocks;
    const long zbeg = blin * zpb;
    const long zend = (zbeg + zpb < zcount) ? (zbeg + zpb) : zcount;
    const long zpt = (zpb + NROWTILES - 1) / NROWTILES;
    const float4 z4 = make_float4(0.f, 0.f, 0.f, 0.f);

    // cp.async staging: thread t copies float4 elements {t, t+256, ... t+1792}
    const uint32_t sbuf0 = smem_u32(smem);
    const uint32_t sbuf1 = sbuf0 + 32768;

    // Prologue: stage tile 0 into buffer 0
    {
        const float4* xsrc = (const float4*)Xb;
#pragma unroll
        for (int i = 0; i < 8; i++)
            cp_async16(sbuf0 + 16 * (tid + 256 * i), xsrc + tid + 256 * i);
        cp_commit();
    }

    for (int tile = 0; tile < NROWTILES; tile++) {
        // Stage next tile into the other buffer, then wait for current tile
        if (tile + 1 < NROWTILES) {
            const float4* xsrc = (const float4*)Xb + (size_t)(tile + 1) * (128 * 16);
            uint32_t dst = ((tile + 1) & 1) ? sbuf1 : sbuf0;
#pragma unroll
            for (int i = 0; i < 8; i++)
                cp_async16(dst + 16 * (tid + 256 * i), xsrc + tid + 256 * i);
            cp_commit();
            cp_wait<1>();
        } else {
            cp_wait<0>();
        }
        __syncthreads();

        // Paced zero-fill chunk (streaming stores drain under compute)
        {
            long tb = zbeg + (long)tile * zpt;
            long te = tb + zpt; if (te > zend) te = zend;
            for (long i = tb + tid; i < te; i += 256) __stcs(&zbase[i], z4);
        }

        // Warp w processes rows [16w, 16w+16) of this tile; broadcast reads.
        const float* buf = ((tile & 1) ? (smem + 8192) : smem);
        const ulonglong2* xrow = (const ulonglong2*)(buf + warp * (16 * 64));
        const int nbase = tile * 128 + warp * 16;
#pragma unroll 2
        for (int r = 0; r < 16; r += 2) {
            unsigned long long a0 = 0ull, a1 = 0ull, b0 = 0ull, b1 = 0ull;
            const ulonglong2* xr0 = xrow + r * 16;
            const ulonglong2* xr1 = xr0 + 16;
#pragma unroll
            for (int k8 = 0; k8 < 16; k8++) {
                ulonglong2 x0 = xr0[k8];
                ulonglong2 x1 = xr1[k8];
                ffma2(a0, pk[2 * k8],     x0.x);
                ffma2(a1, pk[2 * k8 + 1], x0.y);
                ffma2(b0, pk[2 * k8],     x1.x);
                ffma2(b1, pk[2 * k8 + 1], x1.y);
            }
            float v0 = pairsum(a0) + pairsum(a1);
            float v1 = pairsum(b0) + pairsum(b1);
            top8_insert(topv, topi, v0, nbase + r);
            top8_insert(topv, topi, v1, nbase + r + 1);
        }
        __syncthreads();   // all warps done reading buf before it is re-staged
    }

    // ---- merge phase (reuse smem) ----
    float* candV = smem;                         // [32][65] padded
    int*   candI = (int*)(smem + 32 * 65);       // [32][65]
    float* wV    = smem + 2 * 32 * 65;           // [32][8]
    int*   wI    = (int*)(smem + 2 * 32 * 65 + 32 * 8);

#pragma unroll
    for (int s = 0; s < 8; s++) {
        candV[lane * 65 + warp * 8 + s] = topv[s];
        candI[lane * 65 + warp * 8 + s] = topi[s];
    }
    __syncthreads();

    // One thread per pillar merges 64 candidates -> final top-8 -> softmax
    if (tid < 32) {
        int m = tid;
        float fv[8]; int fi[8];
#pragma unroll
        for (int s = 0; s < 8; s++) { fv[s] = -INFINITY; fi[s] = 0; }
        for (int c = 0; c < 64; c++)
            top8_insert(fv, fi, candV[m * 65 + c], candI[m * 65 + c]);
        float w[8]; float sum = 0.f;
#pragma unroll
        for (int s = 0; s < 8; s++) { w[s] = expf(fv[s] - fv[0]); sum += w[s]; }
        float inv = 1.f / sum;
#pragma unroll
        for (int s = 0; s < 8; s++) { wV[m * 8 + s] = w[s] * inv; wI[m * 8 + s] = fi[s]; }
    }
    __syncthreads();

    // Weighted gather: out[p][d] = sum_k w_k * X[idx_k][d]  (rows are L2-hot)
#pragma unroll
    for (int i = 0; i < 8; i++) {
        int lin = tid + 256 * i;
        int m = lin >> 6, d = lin & 63;
        float s = 0.f;
#pragma unroll
        for (int kk = 0; kk < 8; kk++)
            s += wV[m * 8 + kk] * Xb[(size_t)wI[m * 8 + kk] * 64 + d];
        outb[(size_t)(pBase + m) * 64 + d] = s;
    }
}

// ---------------------------------------------------------------------------
// Scatter: winner pillar per BEV column writes the three dense grids.
// ---------------------------------------------------------------------------
__global__ __launch_bounds__(64) void scatter_kernel(
    const float* __restrict__ pillars, const float* __restrict__ scales,
    const float* __restrict__ posP,    const float* __restrict__ posM,
    const int* __restrict__ idxs,      float* __restrict__ out)
{
    int bp = blockIdx.x;
    int b = bp / Pq, p = bp - b * Pq;
    int col = idxs[bp];
    if (g_winner[b * HWq + col] != p) return;
    int d = threadIdx.x;

    size_t o = (size_t)bp * 64 + d;
    float pilv = pillars[o];
    float scv  = scales[o];
    float ppv  = posP[o];
    float pmv  = posM[o];

    float* sp  = out;               // spatial_features       [B,128,HW]: [pillars ; pos_mem]
    float* spp = out + (size_t)O1;  // spatial_features_point [B,128,HW]: [pillars ; pos_point]
    float* sps = out + (size_t)O2;  // spatial_scale_features [B, 64,HW]

    size_t base = (size_t)b * 128 * HWq + (size_t)d * HWq + col;
    sp [base] = pilv;
    sp [base + (size_t)64 * HWq] = pmv;
    spp[base] = pilv;
    spp[base + (size_t)64 * HWq] = ppv;
    sps[(size_t)b * 64 * HWq + (size_t)d * HWq + col] = scv;
}

// ---------------------------------------------------------------------------
extern "C" void kernel_launch(void* const* d_in, const int* in_sizes, int n_in,
                              void* d_out, int out_size) {
    (void)in_sizes; (void)n_in; (void)out_size;
    const float* pillars = (const float*)d_in[0];   // [B,P,64]
    const float* scales  = (const float*)d_in[1];   // [B,P,64]
    const float* points  = (const float*)d_in[2];   // [B,NP,64]
    const float* W       = (const float*)d_in[3];   // [M,64]
    const int*   idxs    = (const int*)d_in[4];     // [B,P]
    float* out = (float*)d_out;

    cudaFuncSetAttribute(topk_warp_kernel<NPq / 128>,
                         cudaFuncAttributeMaxDynamicSharedMemorySize, SMEM_BYTES);
    cudaFuncSetAttribute(topk_warp_kernel<Mq / 128>,
                         cudaFuncAttributeMaxDynamicSharedMemorySize, SMEM_BYTES);

    // 1) duplicate-index winner resolution (last-write-wins => max p)
    winner_reset_kernel<<<(Bq * HWq + 255) / 256, 256>>>();
    winner_mark_kernel<<<(Bq * Pq + 255) / 256, 256>>>(idxs);

    // 2) fused attention stages; each also zero-fills its share of the
    //    dense spatial region under its compute.
    dim3 grid(Pq / 32, Bq);   // 125 x 2 = 250 blocks
    topk_warp_kernel<NPq / 128><<<grid, 256, SMEM_BYTES>>>(
        pillars, points, out + O3, NPq * 64, (float4*)out, N4P);
    topk_warp_kernel<Mq / 128><<<grid, 256, SMEM_BYTES>>>(
        pillars, W,      out + O4, 0,        (float4*)out + N4P, N4M);

    // 3) scatter winners into the dense BEV grids
    scatter_kernel<<<Bq * Pq, 64>>>(pillars, scales, out + O3, out + O4, idxs, out);
}